// round 14
// baseline (speedup 1.0000x reference)
#include <cuda_runtime.h>
#include <math.h>
#include <stdint.h>

typedef unsigned long long ull;

#define SEQ   1024
#define BATCH 64
#define DIN   256
#define HID   512
#define BUN   512

// ---------------- device scratch (no allocation allowed) ----------------
__device__ __align__(16) float g_H[8 * 512 * 8];                  // [g][j][r]
__device__ __align__(16) float g_P[768 * 512];                    // P = Wb @ Wh
__device__ __align__(16) float g_c0[512];                         // bb@Wh + bh
__device__ unsigned g_ctr[256];                                   // 1 counter / group, 128B apart

// ---------------- packed f32x2 helpers ----------------
__device__ __forceinline__ ull ffma2(ull a, ull b, ull c) {
    ull d; asm("fma.rn.f32x2 %0, %1, %2, %3;" : "=l"(d) : "l"(a), "l"(b), "l"(c)); return d;
}
__device__ __forceinline__ ull add2(ull a, ull b) {
    ull d; asm("add.rn.f32x2 %0, %1, %2;" : "=l"(d) : "l"(a), "l"(b)); return d;
}
__device__ __forceinline__ ull pack2(float x, float y) {
    ull d; asm("mov.b64 %0, {%1, %2};" : "=l"(d) : "f"(x), "f"(y)); return d;
}
__device__ __forceinline__ float2 unpack2(ull a) {
    float2 r; asm("mov.b64 {%0, %1}, %2;" : "=f"(r.x), "=f"(r.y) : "l"(a)); return r;
}

// ---------------- L1-bypassing global access ----------------
__device__ __forceinline__ float4 ldcg4(const float* p) {
    float4 v;
    asm volatile("ld.global.cg.v4.f32 {%0,%1,%2,%3}, [%4];"
                 : "=f"(v.x), "=f"(v.y), "=f"(v.z), "=f"(v.w) : "l"(p));
    return v;
}
__device__ __forceinline__ void stcg8(float* p, ull v) {
    asm volatile("st.global.cg.u64 [%0], %1;" :: "l"(p), "l"(v));
}

// ---------------- init: zero H and counters (every replay) ------
__global__ void __launch_bounds__(256) init_kernel() {
    int t = threadIdx.x;
    g_ctr[t] = 0u;
    for (int i = t; i < 8 * 512 * 8; i += 256) g_H[i] = 0.0f;
}

// ---------------------------------------------------------------------------
// c0[u] = sum_j bb[j] * Wh[j][u] + bh[u]
// ---------------------------------------------------------------------------
__global__ void __launch_bounds__(512) c0_kernel(const float* __restrict__ bb,
                                                 const float* __restrict__ Wh,
                                                 const float* __restrict__ bh) {
    int u = threadIdx.x;
    float s = __ldg(&bh[u]);
#pragma unroll 8
    for (int j = 0; j < BUN; j++)
        s += __ldg(&bb[j]) * __ldg(&Wh[(size_t)j * HID + u]);
    g_c0[u] = s;
}

// ---------------------------------------------------------------------------
// P = Wb @ Wh   (768 x 512, K = 512). grid (8 colblk, 12 rowblk), 256 thr.
// ---------------------------------------------------------------------------
__global__ void __launch_bounds__(256) pmat_kernel(const float* __restrict__ Wb,
                                                   const float* __restrict__ Wh) {
    __shared__ float Asm[64 * 32];   // [r][k]
    __shared__ float Bsm[32 * 64];   // [k][j]
    const int tid = threadIdx.x;
    const int tx  = tid & 15;
    const int ty  = tid >> 4;
    const int jb  = blockIdx.x * 64;
    const int rb  = blockIdx.y * 64;

    float acc[16];
#pragma unroll
    for (int i = 0; i < 16; i++) acc[i] = 0.0f;

    for (int kt = 0; kt < 16; kt++) {
        const int kg = kt * 32;
#pragma unroll
        for (int i = 0; i < 2; i++) {
            int v = tid + 256 * i;
            int r = v >> 3, q = v & 7;
            *(float4*)&Asm[r * 32 + 4 * q] =
                __ldg((const float4*)&Wb[(size_t)(rb + r) * BUN + kg + 4 * q]);
        }
#pragma unroll
        for (int i = 0; i < 2; i++) {
            int v = tid + 256 * i;
            int kk = v >> 4, q = v & 15;
            *(float4*)&Bsm[kk * 64 + 4 * q] =
                __ldg((const float4*)&Wh[(size_t)(kg + kk) * HID + jb + 4 * q]);
        }
        __syncthreads();
#pragma unroll 8
        for (int kk = 0; kk < 32; kk++) {
            float4 b = *(const float4*)&Bsm[kk * 64 + 4 * tx];
            float a0 = Asm[(4 * ty + 0) * 32 + kk];
            float a1 = Asm[(4 * ty + 1) * 32 + kk];
            float a2 = Asm[(4 * ty + 2) * 32 + kk];
            float a3 = Asm[(4 * ty + 3) * 32 + kk];
            acc[0]  += a0 * b.x; acc[1]  += a0 * b.y; acc[2]  += a0 * b.z; acc[3]  += a0 * b.w;
            acc[4]  += a1 * b.x; acc[5]  += a1 * b.y; acc[6]  += a1 * b.z; acc[7]  += a1 * b.w;
            acc[8]  += a2 * b.x; acc[9]  += a2 * b.y; acc[10] += a2 * b.z; acc[11] += a2 * b.w;
            acc[12] += a3 * b.x; acc[13] += a3 * b.y; acc[14] += a3 * b.z; acc[15] += a3 * b.w;
        }
        __syncthreads();
    }
#pragma unroll
    for (int i = 0; i < 4; i++) {
        float4 o = make_float4(acc[4 * i], acc[4 * i + 1], acc[4 * i + 2], acc[4 * i + 3]);
        *(float4*)&g_P[(size_t)(rb + 4 * ty + i) * 512 + jb + 4 * tx] = o;
    }
}

// ---------------------------------------------------------------------------
// Persistent recurrent kernel: 128 CTAs = 8 groups x 16 col-blocks.
// R9 skeleton + fused C computation: warps 4-7 compute C_{t+1} = x_{t+1}@N + c0
// for this CTA's 8x32 tile during the reduce/epilogue/barrier shadow.
// No pre_kernel, no g_C.
// Dynamic smem layout (floats):
//   SCR [0, 8320)       HT staged h / RED partials (R9)
//   NT  [8320, 16640)   N transposed: NT[c][k], stride 260 (32 x 260)
//   XS  [16640, 18688)  x rows for t+1: [r 8][k 256]
//   CS  [18688, 19200)  C tiles, parity: [2][r 8][c 32]
// ---------------------------------------------------------------------------
#define SCR_F 8320
#define NT_OFF 8320
#define XS_OFF 16640
#define CS_OFF 18688
#define RECSM  (19200 * 4)
#define RED_STRIDE 130       // ull stride per k-slice row

__global__ void __launch_bounds__(256, 1) rec_kernel(const float* __restrict__ X,
                                                     const float* __restrict__ tau,
                                                     float* __restrict__ out) {
    extern __shared__ __align__(16) float smem[];
    float* SCR = smem;
    float* NT  = smem + NT_OFF;
    float* XS  = smem + XS_OFF;
    float* CS  = smem + CS_OFF;

    const int tid  = threadIdx.x;
    const int lane = tid & 31;
    const int w    = tid >> 5;
    const int g    = blockIdx.x >> 4;   // batch group
    const int cb   = blockIdx.x & 15;   // column block
    const int j0   = cb * 32;
    const int cg   = tid & 7;           // column sub-group (4 cols)
    const int ks   = tid >> 3;          // k-slice 0..31 (16 k each)
    const int c0i  = 4 * cg;

    // --- weights into registers: 16 x float4, held for all 1024 steps ---
    float4 wf[16];
    {
        const float* ws = &g_P[(size_t)(256 + 16 * ks) * 512 + j0 + c0i];
#pragma unroll
        for (int i = 0; i < 16; i++)
            wf[i] = __ldg((const float4*)(ws + (size_t)i * 512));
    }

    // --- one-time NT transpose-load: NT[c][k] = g_P[k][j0+c], k < 256 ---
#pragma unroll
    for (int i = 0; i < 8; i++) {
        int v = tid + 256 * i;          // 0..2047 float4-slots
        int k = v >> 3, q = v & 7;
        float4 p = __ldg((const float4*)&g_P[(size_t)k * 512 + j0 + 4 * q]);
        NT[(4 * q + 0) * 260 + k] = p.x;
        NT[(4 * q + 1) * 260 + k] = p.y;
        NT[(4 * q + 2) * 260 + k] = p.z;
        NT[(4 * q + 3) * 260 + k] = p.w;
    }

    // --- hoisted epilogue state (output-owning threads: tid < 128) ---
    float ertau = 0.0f;
    ull h_reg = 0ull;
    float *ghp = g_H, *o0 = out, *o1 = out;
    int erp = 0, ec = 0;
    if (tid < 128) {
        erp = tid >> 5;                 // row pair (rows 2erp, 2erp+1)
        ec = tid & 31;
        int ej = j0 + ec;
        ertau = 1.0f / __ldg(&tau[ej]);
        ghp = g_H + (size_t)g * 4096 + ej * 8 + 2 * erp;
        int b0 = g * 8 + 2 * erp;
        o0 = out + ((size_t)b0 * SEQ) * HID + ej;
        o1 = out + ((size_t)(b0 + 1) * SEQ) * HID + ej;
    }

    // --- mini-GEMM state (warps 4-7: C producer for t+1) ---
    float c0v = 0.0f;
    const float *xrow0 = X, *xrow1 = X;
    int r0 = 0;
    if (w >= 4) {
        r0 = 2 * (w - 4);               // this warp's 2 batch rows
        c0v = __ldg(&g_c0[j0 + lane]);
        xrow0 = X + ((size_t)(8 * g + r0) * SEQ) * DIN;       // + t*DIN
        xrow1 = X + ((size_t)(8 * g + r0 + 1) * SEQ) * DIN;
    }

    const float* gHbase = g_H + (size_t)g * 4096;
    unsigned* ctr = &g_ctr[g * 32];
    unsigned bt = 0;
    ull* RED = (ull*)SCR;
    const float* ht_p = SCR + ks * 136;

    __syncthreads();                    // NT staged

    // --- prologue: C_0 into CS parity 0 (warps 4-7) ---
    if (w >= 4) {
        const float4* xg0 = (const float4*)xrow0;   // t = 0
        const float4* xg1 = (const float4*)xrow1;
        float4* xs0 = (float4*)&XS[r0 * 256];
        float4* xs1 = (float4*)&XS[(r0 + 1) * 256];
        xs0[lane] = __ldg(&xg0[lane]); xs0[lane + 32] = __ldg(&xg0[lane + 32]);
        xs1[lane] = __ldg(&xg1[lane]); xs1[lane + 32] = __ldg(&xg1[lane + 32]);
        __syncwarp();
        ull a0 = 0ull, a1 = 0ull;
        const float* ntp = &NT[lane * 260];
#pragma unroll 8
        for (int i = 0; i < 64; i++) {
            ulonglong2 nv = *(const ulonglong2*)(ntp + 4 * i);
            ulonglong2 x0 = *(const ulonglong2*)&XS[r0 * 256 + 4 * i];
            ulonglong2 x1 = *(const ulonglong2*)&XS[(r0 + 1) * 256 + 4 * i];
            a0 = ffma2(nv.x, x0.x, a0); a0 = ffma2(nv.y, x0.y, a0);
            a1 = ffma2(nv.x, x1.x, a1); a1 = ffma2(nv.y, x1.y, a1);
        }
        float2 f0 = unpack2(a0), f1 = unpack2(a1);
        CS[r0 * 32 + lane]       = f0.x + f0.y + c0v;
        CS[(r0 + 1) * 32 + lane] = f1.x + f1.y + c0v;
    }
    __syncthreads();                    // CS[par 0] ready

    for (int t = 0; t < SEQ; t++) {
        // stage h into skewed transposed layout HT[(k>>4)*136 + (k&15)*8 + r]
#pragma unroll
        for (int i = 0; i < 4; i++) {
            int v = tid + 256 * i;      // float4-slot over [j][r] = 4096 floats
            float4 d = ldcg4(gHbase + 4 * v);
            int k = v >> 1, half = v & 1;
            *(float4*)&SCR[(k >> 4) * 136 + (k & 15) * 8 + 4 * half] = d;
        }
        __syncthreads();
        {
            ull acc[16];
#pragma unroll
            for (int i = 0; i < 16; i++) acc[i] = 0ull;
#pragma unroll
            for (int i = 0; i < 16; i++) {
                ulonglong2 hA = *(const ulonglong2*)(ht_p + 8 * i);
                ulonglong2 hB = *(const ulonglong2*)(ht_p + 8 * i + 4);
                float4 wv = wf[i];
                ull w0 = pack2(wv.x, wv.x), w1 = pack2(wv.y, wv.y);
                ull w2 = pack2(wv.z, wv.z), w3 = pack2(wv.w, wv.w);
                acc[0]  = ffma2(hA.x, w0, acc[0]);
                acc[1]  = ffma2(hA.x, w1, acc[1]);
                acc[2]  = ffma2(hA.x, w2, acc[2]);
                acc[3]  = ffma2(hA.x, w3, acc[3]);
                acc[4]  = ffma2(hA.y, w0, acc[4]);
                acc[5]  = ffma2(hA.y, w1, acc[5]);
                acc[6]  = ffma2(hA.y, w2, acc[6]);
                acc[7]  = ffma2(hA.y, w3, acc[7]);
                acc[8]  = ffma2(hB.x, w0, acc[8]);
                acc[9]  = ffma2(hB.x, w1, acc[9]);
                acc[10] = ffma2(hB.x, w2, acc[10]);
                acc[11] = ffma2(hB.x, w3, acc[11]);
                acc[12] = ffma2(hB.y, w0, acc[12]);
                acc[13] = ffma2(hB.y, w1, acc[13]);
                acc[14] = ffma2(hB.y, w2, acc[14]);
                acc[15] = ffma2(hB.y, w3, acc[15]);
            }
            __syncthreads();            // done reading HT before RED overwrite
#pragma unroll
            for (int rp = 0; rp < 4; rp++) {
                ulonglong2 v0, v1;
                v0.x = acc[rp * 4 + 0]; v0.y = acc[rp * 4 + 1];
                v1.x = acc[rp * 4 + 2]; v1.y = acc[rp * 4 + 3];
                *(ulonglong2*)&RED[ks * RED_STRIDE + rp * 32 + c0i]     = v0;
                *(ulonglong2*)&RED[ks * RED_STRIDE + rp * 32 + c0i + 2] = v1;
            }
        }
        __syncthreads();

        if (tid < 128) {
            // ---- reduce + epilogue ----
            const ull* rb = RED + tid;
            ull s0 = rb[0];
            ull s1 = rb[RED_STRIDE];
            ull s2 = rb[2 * RED_STRIDE];
            ull s3 = rb[3 * RED_STRIDE];
#pragma unroll
            for (int i = 4; i < 32; i += 4) {
                s0 = add2(s0, rb[(i + 0) * RED_STRIDE]);
                s1 = add2(s1, rb[(i + 1) * RED_STRIDE]);
                s2 = add2(s2, rb[(i + 2) * RED_STRIDE]);
                s3 = add2(s3, rb[(i + 3) * RED_STRIDE]);
            }
            float2 z = unpack2(add2(add2(s0, s1), add2(s2, s3)));
            const float* cs = CS + (t & 1) * 256;
            float d0 = tanhf(z.x + cs[(2 * erp) * 32 + ec]);
            float d1 = tanhf(z.y + cs[(2 * erp + 1) * 32 + ec]);
            float2 h = unpack2(h_reg);
            float hn0 = h.x + (d0 - h.x) * ertau;
            float hn1 = h.y + (d1 - h.y) * ertau;
            h_reg = pack2(hn0, hn1);
            stcg8(ghp, h_reg);
            o0[(size_t)t * HID] = hn0;
            o1[(size_t)t * HID] = hn1;
            __threadfence();            // writers only: release h before arrival
        } else if (t + 1 < SEQ) {
            // ---- mini-GEMM: C_{t+1} into CS parity (t+1)&1 (barrier shadow) ----
            const float4* xg0 = (const float4*)(xrow0 + (size_t)(t + 1) * DIN);
            const float4* xg1 = (const float4*)(xrow1 + (size_t)(t + 1) * DIN);
            float4* xs0 = (float4*)&XS[r0 * 256];
            float4* xs1 = (float4*)&XS[(r0 + 1) * 256];
            xs0[lane] = __ldg(&xg0[lane]); xs0[lane + 32] = __ldg(&xg0[lane + 32]);
            xs1[lane] = __ldg(&xg1[lane]); xs1[lane + 32] = __ldg(&xg1[lane + 32]);
            __syncwarp();
            ull a0 = 0ull, a1 = 0ull;
            const float* ntp = &NT[lane * 260];
#pragma unroll 8
            for (int i = 0; i < 64; i++) {
                ulonglong2 nv = *(const ulonglong2*)(ntp + 4 * i);
                ulonglong2 x0 = *(const ulonglong2*)&XS[r0 * 256 + 4 * i];
                ulonglong2 x1 = *(const ulonglong2*)&XS[(r0 + 1) * 256 + 4 * i];
                a0 = ffma2(nv.x, x0.x, a0); a0 = ffma2(nv.y, x0.y, a0);
                a1 = ffma2(nv.x, x1.x, a1); a1 = ffma2(nv.y, x1.y, a1);
            }
            float2 f0 = unpack2(a0), f1 = unpack2(a1);
            float* cs = CS + ((t + 1) & 1) * 256;
            cs[r0 * 32 + lane]       = f0.x + f0.y + c0v;
            cs[(r0 + 1) * 32 + lane] = f1.x + f1.y + c0v;
        }
        __syncthreads();                // h fenced by writers; CS_{t+1} staged
        bt += 16;
        if (tid == 0) {
            asm volatile("red.release.gpu.global.add.u32 [%0], %1;" :: "l"(ctr), "r"(1u) : "memory");
            unsigned v;
            do {
                asm volatile("ld.acquire.gpu.global.u32 %0, [%1];" : "=r"(v) : "l"(ctr) : "memory");
            } while (v < bt);
        }
        __syncthreads();
    }
}

// ---------------------------------------------------------------------------
extern "C" void kernel_launch(void* const* d_in, const int* in_sizes, int n_in,
                              void* d_out, int out_size) {
    (void)in_sizes; (void)n_in; (void)out_size;
    const float* X   = (const float*)d_in[0];
    const float* Wb  = (const float*)d_in[1];
    const float* bb  = (const float*)d_in[2];
    const float* Wh  = (const float*)d_in[3];
    const float* bh  = (const float*)d_in[4];
    const float* tau = (const float*)d_in[5];
    float* out = (float*)d_out;

    cudaFuncSetAttribute(rec_kernel, cudaFuncAttributeMaxDynamicSharedMemorySize, RECSM);

    init_kernel<<<1, 256>>>();
    c0_kernel<<<1, 512>>>(bb, Wh, bh);
    dim3 pgrid(8, 12);
    pmat_kernel<<<pgrid, 256>>>(Wb, Wh);
    rec_kernel<<<128, 256, RECSM>>>(X, tau, out);
}

// round 15
// speedup vs baseline: 1.1522x; 1.1522x over previous
#include <cuda_runtime.h>
#include <math.h>
#include <stdint.h>

typedef unsigned long long ull;

#define SEQ   1024
#define BATCH 64
#define DIN   256
#define HID   512
#define BUN   512

// ---------------- device scratch (no allocation allowed) ----------------
__device__ __align__(16) float g_H[8 * 512 * 8];                  // [g][j][r]
__device__ __align__(16) float g_P[768 * 512];                    // P = Wb @ Wh
__device__ __align__(16) float g_c0[512];                         // bb@Wh + bh
__device__ unsigned g_ctr[256];                                   // 1 counter / group, 128B apart

// ---------------- packed f32x2 helpers ----------------
__device__ __forceinline__ ull ffma2(ull a, ull b, ull c) {
    ull d; asm("fma.rn.f32x2 %0, %1, %2, %3;" : "=l"(d) : "l"(a), "l"(b), "l"(c)); return d;
}
__device__ __forceinline__ ull add2(ull a, ull b) {
    ull d; asm("add.rn.f32x2 %0, %1, %2;" : "=l"(d) : "l"(a), "l"(b)); return d;
}
__device__ __forceinline__ ull pack2(float x, float y) {
    ull d; asm("mov.b64 %0, {%1, %2};" : "=l"(d) : "f"(x), "f"(y)); return d;
}
__device__ __forceinline__ float2 unpack2(ull a) {
    float2 r; asm("mov.b64 {%0, %1}, %2;" : "=f"(r.x), "=f"(r.y) : "l"(a)); return r;
}

// ---------------- L1-bypassing global access ----------------
__device__ __forceinline__ float4 ldcg4(const float* p) {
    float4 v;
    asm volatile("ld.global.cg.v4.f32 {%0,%1,%2,%3}, [%4];"
                 : "=f"(v.x), "=f"(v.y), "=f"(v.z), "=f"(v.w) : "l"(p));
    return v;
}
__device__ __forceinline__ void stcg8(float* p, ull v) {
    asm volatile("st.global.cg.u64 [%0], %1;" :: "l"(p), "l"(v));
}

// ---------------- init: zero H and counters (every replay) ------
__global__ void __launch_bounds__(256) init_kernel() {
    int t = threadIdx.x;
    g_ctr[t] = 0u;
    for (int i = t; i < 8 * 512 * 8; i += 256) g_H[i] = 0.0f;
}

// ---------------------------------------------------------------------------
// c0[u] = sum_j bb[j] * Wh[j][u] + bh[u]
// ---------------------------------------------------------------------------
__global__ void __launch_bounds__(512) c0_kernel(const float* __restrict__ bb,
                                                 const float* __restrict__ Wh,
                                                 const float* __restrict__ bh) {
    int u = threadIdx.x;
    float s = __ldg(&bh[u]);
#pragma unroll 8
    for (int j = 0; j < BUN; j++)
        s += __ldg(&bb[j]) * __ldg(&Wh[(size_t)j * HID + u]);
    g_c0[u] = s;
}

// ---------------------------------------------------------------------------
// P = Wb @ Wh   (768 x 512, K = 512). grid (8 colblk, 12 rowblk), 256 thr.
// ---------------------------------------------------------------------------
__global__ void __launch_bounds__(256) pmat_kernel(const float* __restrict__ Wb,
                                                   const float* __restrict__ Wh) {
    __shared__ float Asm[64 * 32];   // [r][k]
    __shared__ float Bsm[32 * 64];   // [k][j]
    const int tid = threadIdx.x;
    const int tx  = tid & 15;
    const int ty  = tid >> 4;
    const int jb  = blockIdx.x * 64;
    const int rb  = blockIdx.y * 64;

    float acc[16];
#pragma unroll
    for (int i = 0; i < 16; i++) acc[i] = 0.0f;

    for (int kt = 0; kt < 16; kt++) {
        const int kg = kt * 32;
#pragma unroll
        for (int i = 0; i < 2; i++) {
            int v = tid + 256 * i;
            int r = v >> 3, q = v & 7;
            *(float4*)&Asm[r * 32 + 4 * q] =
                __ldg((const float4*)&Wb[(size_t)(rb + r) * BUN + kg + 4 * q]);
        }
#pragma unroll
        for (int i = 0; i < 2; i++) {
            int v = tid + 256 * i;
            int kk = v >> 4, q = v & 15;
            *(float4*)&Bsm[kk * 64 + 4 * q] =
                __ldg((const float4*)&Wh[(size_t)(kg + kk) * HID + jb + 4 * q]);
        }
        __syncthreads();
#pragma unroll 8
        for (int kk = 0; kk < 32; kk++) {
            float4 b = *(const float4*)&Bsm[kk * 64 + 4 * tx];
            float a0 = Asm[(4 * ty + 0) * 32 + kk];
            float a1 = Asm[(4 * ty + 1) * 32 + kk];
            float a2 = Asm[(4 * ty + 2) * 32 + kk];
            float a3 = Asm[(4 * ty + 3) * 32 + kk];
            acc[0]  += a0 * b.x; acc[1]  += a0 * b.y; acc[2]  += a0 * b.z; acc[3]  += a0 * b.w;
            acc[4]  += a1 * b.x; acc[5]  += a1 * b.y; acc[6]  += a1 * b.z; acc[7]  += a1 * b.w;
            acc[8]  += a2 * b.x; acc[9]  += a2 * b.y; acc[10] += a2 * b.z; acc[11] += a2 * b.w;
            acc[12] += a3 * b.x; acc[13] += a3 * b.y; acc[14] += a3 * b.z; acc[15] += a3 * b.w;
        }
        __syncthreads();
    }
#pragma unroll
    for (int i = 0; i < 4; i++) {
        float4 o = make_float4(acc[4 * i], acc[4 * i + 1], acc[4 * i + 2], acc[4 * i + 3]);
        *(float4*)&g_P[(size_t)(rb + 4 * ty + i) * 512 + jb + 4 * tx] = o;
    }
}

// ---------------------------------------------------------------------------
// Persistent recurrent kernel: 128 CTAs = 8 groups x 16 col-blocks.
// Fused C: warps 4-7 compute C_{t+1} = x_{t+1}@N + c0 CONCURRENTLY with
// tid0's barrier release+spin (not before it — that was R13's bug).
// Dynamic smem layout (floats):
//   SCR [0, 8320)       HT staged h / RED partials
//   NT  [8320, 16640)   N transposed: NT[c][k], stride 260 (32 x 260)
//   XS  [16640, 18688)  x rows for t+1: [r 8][k 256]
//   CS  [18688, 19200)  C tiles, parity: [2][r 8][c 32]
// ---------------------------------------------------------------------------
#define SCR_F 8320
#define NT_OFF 8320
#define XS_OFF 16640
#define CS_OFF 18688
#define RECSM  (19200 * 4)
#define RED_STRIDE 130       // ull stride per k-slice row

__global__ void __launch_bounds__(256, 1) rec_kernel(const float* __restrict__ X,
                                                     const float* __restrict__ tau,
                                                     float* __restrict__ out) {
    extern __shared__ __align__(16) float smem[];
    float* SCR = smem;
    float* NT  = smem + NT_OFF;
    float* XS  = smem + XS_OFF;
    float* CS  = smem + CS_OFF;

    const int tid  = threadIdx.x;
    const int lane = tid & 31;
    const int w    = tid >> 5;
    const int g    = blockIdx.x >> 4;   // batch group
    const int cb   = blockIdx.x & 15;   // column block
    const int j0   = cb * 32;
    const int cg   = tid & 7;           // column sub-group (4 cols)
    const int ks   = tid >> 3;          // k-slice 0..31 (16 k each)
    const int c0i  = 4 * cg;

    // --- weights into registers: 16 x float4, held for all 1024 steps ---
    float4 wf[16];
    {
        const float* ws = &g_P[(size_t)(256 + 16 * ks) * 512 + j0 + c0i];
#pragma unroll
        for (int i = 0; i < 16; i++)
            wf[i] = __ldg((const float4*)(ws + (size_t)i * 512));
    }

    // --- one-time NT transpose-load: NT[c][k] = g_P[k][j0+c], k < 256 ---
#pragma unroll
    for (int i = 0; i < 8; i++) {
        int v = tid + 256 * i;          // 0..2047 float4-slots
        int k = v >> 3, q = v & 7;
        float4 p = __ldg((const float4*)&g_P[(size_t)k * 512 + j0 + 4 * q]);
        NT[(4 * q + 0) * 260 + k] = p.x;
        NT[(4 * q + 1) * 260 + k] = p.y;
        NT[(4 * q + 2) * 260 + k] = p.z;
        NT[(4 * q + 3) * 260 + k] = p.w;
    }

    // --- hoisted epilogue state (output-owning threads: tid < 128) ---
    float ertau = 0.0f;
    ull h_reg = 0ull;
    float *ghp = g_H, *o0 = out, *o1 = out;
    int erp = 0, ec = 0;
    if (tid < 128) {
        erp = tid >> 5;                 // row pair (rows 2erp, 2erp+1)
        ec = tid & 31;
        int ej = j0 + ec;
        ertau = 1.0f / __ldg(&tau[ej]);
        ghp = g_H + (size_t)g * 4096 + ej * 8 + 2 * erp;
        int b0 = g * 8 + 2 * erp;
        o0 = out + ((size_t)b0 * SEQ) * HID + ej;
        o1 = out + ((size_t)(b0 + 1) * SEQ) * HID + ej;
    }

    // --- mini-GEMM state (warps 4-7: C producer for t+1) ---
    float c0v = 0.0f;
    const float *xrow0 = X, *xrow1 = X;
    int r0 = 0;
    if (w >= 4) {
        r0 = 2 * (w - 4);               // this warp's 2 batch rows
        c0v = __ldg(&g_c0[j0 + lane]);
        xrow0 = X + ((size_t)(8 * g + r0) * SEQ) * DIN;       // + t*DIN
        xrow1 = X + ((size_t)(8 * g + r0 + 1) * SEQ) * DIN;
    }

    const float* gHbase = g_H + (size_t)g * 4096;
    unsigned* ctr = &g_ctr[g * 32];
    unsigned bt = 0;
    ull* RED = (ull*)SCR;
    const float* ht_p = SCR + ks * 136;

    __syncthreads();                    // NT staged

    // --- prologue: C_0 into CS parity 0 (warps 4-7) ---
    if (w >= 4) {
        const float4* xg0 = (const float4*)xrow0;   // t = 0
        const float4* xg1 = (const float4*)xrow1;
        float4* xs0 = (float4*)&XS[r0 * 256];
        float4* xs1 = (float4*)&XS[(r0 + 1) * 256];
        xs0[lane] = __ldg(&xg0[lane]); xs0[lane + 32] = __ldg(&xg0[lane + 32]);
        xs1[lane] = __ldg(&xg1[lane]); xs1[lane + 32] = __ldg(&xg1[lane + 32]);
        __syncwarp();
        ull a0 = 0ull, a1 = 0ull;
        const float* ntp = &NT[lane * 260];
#pragma unroll 8
        for (int i = 0; i < 64; i++) {
            ulonglong2 nv = *(const ulonglong2*)(ntp + 4 * i);
            ulonglong2 x0 = *(const ulonglong2*)&XS[r0 * 256 + 4 * i];
            ulonglong2 x1 = *(const ulonglong2*)&XS[(r0 + 1) * 256 + 4 * i];
            a0 = ffma2(nv.x, x0.x, a0); a0 = ffma2(nv.y, x0.y, a0);
            a1 = ffma2(nv.x, x1.x, a1); a1 = ffma2(nv.y, x1.y, a1);
        }
        float2 f0 = unpack2(a0), f1 = unpack2(a1);
        CS[r0 * 32 + lane]       = f0.x + f0.y + c0v;
        CS[(r0 + 1) * 32 + lane] = f1.x + f1.y + c0v;
    }
    __syncthreads();                    // CS[par 0] ready

    for (int t = 0; t < SEQ; t++) {
        // prefetch x_{t+1} into registers (warps 4-7) — DRAM latency hidden
        // under stage + kloop; consumed in the mini-GEMM phase below.
        float4 xp0, xp1, xp2, xp3;
        if (w >= 4 && t + 1 < SEQ) {
            const float4* xg0 = (const float4*)(xrow0 + (size_t)(t + 1) * DIN);
            const float4* xg1 = (const float4*)(xrow1 + (size_t)(t + 1) * DIN);
            xp0 = __ldg(&xg0[lane]); xp1 = __ldg(&xg0[lane + 32]);
            xp2 = __ldg(&xg1[lane]); xp3 = __ldg(&xg1[lane + 32]);
        }

        // stage h into skewed transposed layout HT[(k>>4)*136 + (k&15)*8 + r]
#pragma unroll
        for (int i = 0; i < 4; i++) {
            int v = tid + 256 * i;      // float4-slot over [j][r] = 4096 floats
            float4 d = ldcg4(gHbase + 4 * v);
            int k = v >> 1, half = v & 1;
            *(float4*)&SCR[(k >> 4) * 136 + (k & 15) * 8 + 4 * half] = d;
        }
        __syncthreads();
        {
            ull acc[16];
#pragma unroll
            for (int i = 0; i < 16; i++) acc[i] = 0ull;
#pragma unroll
            for (int i = 0; i < 16; i++) {
                ulonglong2 hA = *(const ulonglong2*)(ht_p + 8 * i);
                ulonglong2 hB = *(const ulonglong2*)(ht_p + 8 * i + 4);
                float4 wv = wf[i];
                ull w0 = pack2(wv.x, wv.x), w1 = pack2(wv.y, wv.y);
                ull w2 = pack2(wv.z, wv.z), w3 = pack2(wv.w, wv.w);
                acc[0]  = ffma2(hA.x, w0, acc[0]);
                acc[1]  = ffma2(hA.x, w1, acc[1]);
                acc[2]  = ffma2(hA.x, w2, acc[2]);
                acc[3]  = ffma2(hA.x, w3, acc[3]);
                acc[4]  = ffma2(hA.y, w0, acc[4]);
                acc[5]  = ffma2(hA.y, w1, acc[5]);
                acc[6]  = ffma2(hA.y, w2, acc[6]);
                acc[7]  = ffma2(hA.y, w3, acc[7]);
                acc[8]  = ffma2(hB.x, w0, acc[8]);
                acc[9]  = ffma2(hB.x, w1, acc[9]);
                acc[10] = ffma2(hB.x, w2, acc[10]);
                acc[11] = ffma2(hB.x, w3, acc[11]);
                acc[12] = ffma2(hB.y, w0, acc[12]);
                acc[13] = ffma2(hB.y, w1, acc[13]);
                acc[14] = ffma2(hB.y, w2, acc[14]);
                acc[15] = ffma2(hB.y, w3, acc[15]);
            }
            __syncthreads();            // done reading HT before RED overwrite
#pragma unroll
            for (int rp = 0; rp < 4; rp++) {
                ulonglong2 v0, v1;
                v0.x = acc[rp * 4 + 0]; v0.y = acc[rp * 4 + 1];
                v1.x = acc[rp * 4 + 2]; v1.y = acc[rp * 4 + 3];
                *(ulonglong2*)&RED[ks * RED_STRIDE + rp * 32 + c0i]     = v0;
                *(ulonglong2*)&RED[ks * RED_STRIDE + rp * 32 + c0i + 2] = v1;
            }
        }
        __syncthreads();
        bt += 16;

        if (tid < 128) {
            // ---- reduce + epilogue + barrier (warps 0-3) ----
            const ull* rb = RED + tid;
            ull s0 = rb[0];
            ull s1 = rb[RED_STRIDE];
            ull s2 = rb[2 * RED_STRIDE];
            ull s3 = rb[3 * RED_STRIDE];
#pragma unroll
            for (int i = 4; i < 32; i += 4) {
                s0 = add2(s0, rb[(i + 0) * RED_STRIDE]);
                s1 = add2(s1, rb[(i + 1) * RED_STRIDE]);
                s2 = add2(s2, rb[(i + 2) * RED_STRIDE]);
                s3 = add2(s3, rb[(i + 3) * RED_STRIDE]);
            }
            float2 z = unpack2(add2(add2(s0, s1), add2(s2, s3)));
            const float* cs = CS + (t & 1) * 256;
            float d0 = tanhf(z.x + cs[(2 * erp) * 32 + ec]);
            float d1 = tanhf(z.y + cs[(2 * erp + 1) * 32 + ec]);
            float2 h = unpack2(h_reg);
            float hn0 = h.x + (d0 - h.x) * ertau;
            float hn1 = h.y + (d1 - h.y) * ertau;
            h_reg = pack2(hn0, hn1);
            stcg8(ghp, h_reg);
            o0[(size_t)t * HID] = hn0;
            o1[(size_t)t * HID] = hn1;
            __threadfence();            // release h (gpu scope)
            asm volatile("bar.sync 1, 128;" ::: "memory");  // all writers fenced
            if (tid == 0) {
                asm volatile("red.release.gpu.global.add.u32 [%0], %1;" :: "l"(ctr), "r"(1u) : "memory");
                unsigned v;
                do {
                    asm volatile("ld.acquire.gpu.global.u32 %0, [%1];" : "=r"(v) : "l"(ctr) : "memory");
                } while (v < bt);
            }
        } else if (t + 1 < SEQ) {
            // ---- mini-GEMM C_{t+1} (warps 4-7), concurrent with the spin ----
            float4* xs0 = (float4*)&XS[r0 * 256];
            float4* xs1 = (float4*)&XS[(r0 + 1) * 256];
            xs0[lane] = xp0; xs0[lane + 32] = xp1;
            xs1[lane] = xp2; xs1[lane + 32] = xp3;
            __syncwarp();
            ull a0 = 0ull, a1 = 0ull;
            const float* ntp = &NT[lane * 260];
#pragma unroll 8
            for (int i = 0; i < 64; i++) {
                ulonglong2 nv = *(const ulonglong2*)(ntp + 4 * i);
                ulonglong2 x0 = *(const ulonglong2*)&XS[r0 * 256 + 4 * i];
                ulonglong2 x1 = *(const ulonglong2*)&XS[(r0 + 1) * 256 + 4 * i];
                a0 = ffma2(nv.x, x0.x, a0); a0 = ffma2(nv.y, x0.y, a0);
                a1 = ffma2(nv.x, x1.x, a1); a1 = ffma2(nv.y, x1.y, a1);
            }
            float2 f0 = unpack2(a0), f1 = unpack2(a1);
            float* cs = CS + ((t + 1) & 1) * 256;
            cs[r0 * 32 + lane]       = f0.x + f0.y + c0v;
            cs[(r0 + 1) * 32 + lane] = f1.x + f1.y + c0v;
        }
        __syncthreads();                // join: barrier passed AND CS_{t+1} staged
    }
}

// ---------------------------------------------------------------------------
extern "C" void kernel_launch(void* const* d_in, const int* in_sizes, int n_in,
                              void* d_out, int out_size) {
    (void)in_sizes; (void)n_in; (void)out_size;
    const float* X   = (const float*)d_in[0];
    const float* Wb  = (const float*)d_in[1];
    const float* bb  = (const float*)d_in[2];
    const float* Wh  = (const float*)d_in[3];
    const float* bh  = (const float*)d_in[4];
    const float* tau = (const float*)d_in[5];
    float* out = (float*)d_out;

    cudaFuncSetAttribute(rec_kernel, cudaFuncAttributeMaxDynamicSharedMemorySize, RECSM);

    init_kernel<<<1, 256>>>();
    c0_kernel<<<1, 512>>>(bb, Wh, bh);
    dim3 pgrid(8, 12);
    pmat_kernel<<<pgrid, 256>>>(Wb, Wh);
    rec_kernel<<<128, 256, RECSM>>>(X, tau, out);
}